// round 8
// baseline (speedup 1.0000x reference)
#include <cuda_runtime.h>
#include <math.h>

// Problem constants
#define NB      16
#define HW      262144           // 512*512
#define KRANK   104856u          // int(512*512*0.4 - 1)
#define NBINS   16384            // value-space bins: bin = min(16383, int(gray*16384))
#define CAP     2048             // per-batch boundary-pixel capacity (expected ~24)
#define P1BLOCKS 1024            // 64 per batch
#define P3BLOCKS 1024            // 64 per batch
#define TOTAL_ELEMS (16.0*3.0*512.0*512.0)

// Device scratch (.bss zero-init; self-resetting each replay)
__device__ unsigned int g_hist[NB * NBINS];       // 1 MB
__device__ unsigned int g_bin[NB];
__device__ unsigned int g_rank[NB];
__device__ unsigned int g_bnd_cnt[NB];
__device__ float        g_bnd_g[NB * CAP];
__device__ float        g_bnd_d[NB * CAP];
__device__ float        g_partial[P3BLOCKS];
__device__ unsigned int g_done1[NB];
__device__ unsigned int g_done2;

__device__ __forceinline__ unsigned int gray_bin(float g) {
    int v = (int)(g * 16384.0f);
    if (v > NBINS - 1) v = NBINS - 1;
    if (v < 0) v = 0;
    return (unsigned int)v;
}

// ---------------------------------------------------------------------------
// K1: value-space histogram of gray; per-batch LAST block runs bin selection.
// 1024 blocks (64/batch) x 256 thr; 16 px/thread.
// ---------------------------------------------------------------------------
__global__ void k1_hist_select(const float* __restrict__ yp) {
    int b = blockIdx.x >> 6;
    int r = blockIdx.x & 63;
    int t = threadIdx.x;

    const float4* c0 = (const float4*)yp + (size_t)b * 3 * (HW/4) + 0 * (HW/4) + r * 1024;
    const float4* c1 = (const float4*)yp + (size_t)b * 3 * (HW/4) + 1 * (HW/4) + r * 1024;
    const float4* c2 = (const float4*)yp + (size_t)b * 3 * (HW/4) + 2 * (HW/4) + r * 1024;
    unsigned int* h = g_hist + (size_t)b * NBINS;

    #pragma unroll
    for (int q = 0; q < 4; q++) {
        int o = t + q * 256;
        float4 a = c0[o], x = c1[o], y = c2[o];
        float g0 = (a.x + x.x + y.x) / 3.0f;
        float g1 = (a.y + x.y + y.y) / 3.0f;
        float g2 = (a.z + x.z + y.z) / 3.0f;
        float g3 = (a.w + x.w + y.w) / 3.0f;
        atomicAdd(&h[gray_bin(g0)], 1u);
        atomicAdd(&h[gray_bin(g1)], 1u);
        atomicAdd(&h[gray_bin(g2)], 1u);
        atomicAdd(&h[gray_bin(g3)], 1u);
    }

    // --- per-batch last-block handshake ---
    __threadfence();
    __shared__ unsigned int s_ticket;
    __syncthreads();
    if (t == 0) s_ticket = atomicAdd(&g_done1[b], 1u);
    __syncthreads();
    if (s_ticket != 63u) return;
    if (t == 0) g_done1[b] = 0u;            // reset for next replay
    __threadfence();

    // --- inline select: find bin containing rank KRANK (256 threads) ---
    const uint4* h4 = (const uint4*)h;      // 4096 uint4
    __shared__ unsigned int partial[64];
    __shared__ unsigned int fine[256];
    __shared__ int s_chunk;
    __shared__ unsigned int s_rem;

    int warp = t >> 5;
    int lane = t & 31;

    #pragma unroll
    for (int it = 0; it < 8; it++) {
        int c = warp + 8 * it;
        uint4 v1 = h4[c * 64 + lane];
        uint4 v2 = h4[c * 64 + 32 + lane];
        unsigned int s = v1.x+v1.y+v1.z+v1.w + v2.x+v2.y+v2.z+v2.w;
        #pragma unroll
        for (int o = 16; o > 0; o >>= 1) s += __shfl_down_sync(0xFFFFFFFFu, s, o);
        if (lane == 0) partial[c] = s;
    }
    __syncthreads();

    if (t == 0) {
        unsigned int k = KRANK, cum = 0;
        int cb = 63;
        for (int j = 0; j < 64; j++) {
            if (k < cum + partial[j]) { cb = j; break; }
            cum += partial[j];
        }
        s_chunk = cb; s_rem = k - cum;
    }
    __syncthreads();

    int cb = s_chunk;
    fine[t] = h[cb * 256 + t];
    __syncthreads();

    if (t == 0) {
        unsigned int k = s_rem, cum = 0;
        int fb = 255;
        for (int i = 0; i < 256; i++) {
            if (k < cum + fine[i]) { fb = i; break; }
            cum += fine[i];
        }
        g_bin[b]  = (unsigned int)(cb * 256 + fb);
        g_rank[b] = k - cum;                // within-bin rank (0-based)
        __threadfence();                    // publish before K2 consumes
    }
}

// ---------------------------------------------------------------------------
// K2: weighted L1 (bin-level mask, boundary pixels appended) + zero hist slice;
// global LAST block: warp-per-batch exact corrections + final reduction.
// 1024 blocks (64/batch) x 256 thr; 16 px/thread.
// ---------------------------------------------------------------------------
__global__ void k2_loss_final(const float* __restrict__ yt,
                              const float* __restrict__ yp,
                              float* __restrict__ out) {
    int b = blockIdx.x >> 6;
    int r = blockIdx.x & 63;
    int t = threadIdx.x;
    unsigned int selbin = g_bin[b];

    // zero this block's 1KB slice of hist for the next replay (64 uint4)
    if (t < 64)
        ((uint4*)g_hist)[blockIdx.x * 64 + t] = make_uint4(0u, 0u, 0u, 0u);

    size_t base4 = (size_t)b * 3 * (HW/4);
    const float4* p0 = (const float4*)yp + base4 + 0*(HW/4) + r*1024;
    const float4* p1 = (const float4*)yp + base4 + 1*(HW/4) + r*1024;
    const float4* p2 = (const float4*)yp + base4 + 2*(HW/4) + r*1024;
    const float4* q0 = (const float4*)yt + base4 + 0*(HW/4) + r*1024;
    const float4* q1 = (const float4*)yt + base4 + 1*(HW/4) + r*1024;
    const float4* q2 = (const float4*)yt + base4 + 2*(HW/4) + r*1024;

    float s = 0.0f;
    #pragma unroll
    for (int qq = 0; qq < 4; qq++) {
        int o = t + qq * 256;
        float4 a = p0[o], x = p1[o], y = p2[o];
        float4 u = __ldcs(&q0[o]);          // y_true: stream (evict-first)
        float4 v = __ldcs(&q1[o]);
        float4 w = __ldcs(&q2[o]);

        float gr[4], dd[4];
        gr[0] = (a.x + x.x + y.x) / 3.0f;
        gr[1] = (a.y + x.y + y.y) / 3.0f;
        gr[2] = (a.z + x.z + y.z) / 3.0f;
        gr[3] = (a.w + x.w + y.w) / 3.0f;
        dd[0] = fabsf(a.x-u.x) + fabsf(x.x-v.x) + fabsf(y.x-w.x);
        dd[1] = fabsf(a.y-u.y) + fabsf(x.y-v.y) + fabsf(y.y-w.y);
        dd[2] = fabsf(a.z-u.z) + fabsf(x.z-v.z) + fabsf(y.z-w.z);
        dd[3] = fabsf(a.w-u.w) + fabsf(x.w-v.w) + fabsf(y.w-w.w);

        #pragma unroll
        for (int i = 0; i < 4; i++) {
            unsigned int bn = gray_bin(gr[i]);
            float wt = (bn < selbin) ? 0.8f : 0.2f;
            if (bn == selbin) {
                unsigned int p = atomicAdd(&g_bnd_cnt[b], 1u);
                if (p < CAP) {
                    g_bnd_g[(size_t)b * CAP + p] = gr[i];
                    g_bnd_d[(size_t)b * CAP + p] = dd[i];
                }
            }
            s += wt * dd[i];
        }
    }

    #pragma unroll
    for (int o = 16; o > 0; o >>= 1)
        s += __shfl_down_sync(0xFFFFFFFFu, s, o);

    __shared__ float ws[8];
    int lane = t & 31;
    int warp = t >> 5;
    if (lane == 0) ws[warp] = s;
    __syncthreads();
    if (warp == 0) {
        float vv = (lane < 8) ? ws[lane] : 0.0f;
        #pragma unroll
        for (int o = 4; o > 0; o >>= 1)
            vv += __shfl_down_sync(0xFFFFFFFFu, vv, o);
        if (lane == 0) g_partial[blockIdx.x] = vv;
    }

    // --- global last-block handshake ---
    __threadfence();
    __shared__ unsigned int s_ticket;
    __syncthreads();
    if (t == 0) s_ticket = atomicAdd(&g_done2, 1u);
    __syncthreads();
    if (s_ticket != P3BLOCKS - 1) return;
    if (t == 0) g_done2 = 0u;               // reset for next replay
    __threadfence();

    // --- corrections: warp per batch (8 warps, 2 batches each) ---
    __shared__ float s_corr[NB];
    __shared__ float s_kth[NB];
    for (int bb = warp; bb < NB; bb += 8) {
        unsigned int n = g_bnd_cnt[bb];
        if (n > CAP) n = CAP;
        unsigned int k = g_rank[bb];
        const float* bg = g_bnd_g + (size_t)bb * CAP;
        const float* bd = g_bnd_d + (size_t)bb * CAP;

        for (unsigned int i = lane; i < n; i += 32) {
            float v = bg[i];
            unsigned int cl = 0, ce = 0;
            for (unsigned int j = 0; j < n; j++) {
                float w2 = bg[j];
                cl += (w2 < v);
                ce += (w2 == v);
            }
            if (cl <= k && k < cl + ce) s_kth[bb] = v;  // unique value
        }
        __syncwarp();
        float kth = s_kth[bb];
        float c = 0.0f;
        for (unsigned int i = lane; i < n; i += 32)
            if (bg[i] <= kth) c += bd[i];
        #pragma unroll
        for (int o = 16; o > 0; o >>= 1)
            c += __shfl_down_sync(0xFFFFFFFFu, c, o);
        if (lane == 0) {
            s_corr[bb] = 0.6f * c;
            g_bnd_cnt[bb] = 0u;             // reset for next replay
        }
    }
    __syncthreads();

    // --- final reduction of 1024 partials + 16 corrections (double) ---
    double acc = 0.0;
    #pragma unroll
    for (int i = 0; i < P3BLOCKS / 256; i++)
        acc += (double)g_partial[t + i * 256];
    if (t < NB) acc += (double)s_corr[t];

    #pragma unroll
    for (int o = 16; o > 0; o >>= 1)
        acc += __shfl_down_sync(0xFFFFFFFFu, acc, o);

    __shared__ double ds[8];
    if (lane == 0) ds[warp] = acc;
    __syncthreads();
    if (warp == 0) {
        double v = (lane < 8) ? ds[lane] : 0.0;
        #pragma unroll
        for (int o = 4; o > 0; o >>= 1)
            v += __shfl_down_sync(0xFFFFFFFFu, v, o);
        if (lane == 0) out[0] = (float)(v / TOTAL_ELEMS);
    }
}

// ---------------------------------------------------------------------------
extern "C" void kernel_launch(void* const* d_in, const int* in_sizes, int n_in,
                              void* d_out, int out_size) {
    const float* y_true = (const float*)d_in[0];
    const float* y_pred = (const float*)d_in[1];
    float* out = (float*)d_out;

    k1_hist_select<<<P1BLOCKS, 256>>>(y_pred);
    k2_loss_final<<<P3BLOCKS, 256>>>(y_true, y_pred, out);
}

// round 9
// speedup vs baseline: 1.2109x; 1.2109x over previous
#include <cuda_runtime.h>
#include <math.h>

// Problem constants
#define NB      16
#define HW      262144           // 512*512
#define KRANK   104856u          // int(512*512*0.4 - 1)
#define NBINS   16384            // value-space bins: bin = min(16383, int(gray*16384))
#define CAP     2048             // per-batch boundary-pixel capacity (expected ~24)
#define P3BLOCKS 1024
#define TOTAL_ELEMS (16.0*3.0*512.0*512.0)

// Device scratch (.bss zero-init; re-zeroed each replay by finalize)
__device__ unsigned int g_hist[NB * NBINS];       // 1 MB
__device__ unsigned int g_bin[NB];
__device__ unsigned int g_rank[NB];
__device__ unsigned int g_bnd_cnt[NB];
__device__ float        g_bnd_g[NB * CAP];
__device__ float        g_bnd_d[NB * CAP];
__device__ float        g_partial[P3BLOCKS];

__device__ __forceinline__ unsigned int gray_bin(float g) {
    int v = (int)(g * 16384.0f);
    if (v > NBINS - 1) v = NBINS - 1;
    if (v < 0) v = 0;
    return (unsigned int)v;
}

// ---------------------------------------------------------------------------
// K1: value-space histogram of gray = (c0+c1+c2)/3.
// 1024 blocks (64/batch) x 256 thr; 16 px/thread.
// ---------------------------------------------------------------------------
__global__ void pass1_hist(const float* __restrict__ yp) {
    int b = blockIdx.x >> 6;
    int r = blockIdx.x & 63;
    int t = threadIdx.x;

    const float4* c0 = (const float4*)yp + (size_t)b * 3 * (HW/4) + 0 * (HW/4) + r * 1024;
    const float4* c1 = (const float4*)yp + (size_t)b * 3 * (HW/4) + 1 * (HW/4) + r * 1024;
    const float4* c2 = (const float4*)yp + (size_t)b * 3 * (HW/4) + 2 * (HW/4) + r * 1024;
    unsigned int* h = g_hist + (size_t)b * NBINS;

    #pragma unroll
    for (int q = 0; q < 4; q++) {
        int o = t + q * 256;
        float4 a = c0[o], x = c1[o], y = c2[o];
        float g0 = (a.x + x.x + y.x) / 3.0f;
        float g1 = (a.y + x.y + y.y) / 3.0f;
        float g2 = (a.z + x.z + y.z) / 3.0f;
        float g3 = (a.w + x.w + y.w) / 3.0f;
        atomicAdd(&h[gray_bin(g0)], 1u);
        atomicAdd(&h[gray_bin(g1)], 1u);
        atomicAdd(&h[gray_bin(g2)], 1u);
        atomicAdd(&h[gray_bin(g3)], 1u);
    }
}

// ---------------------------------------------------------------------------
// K2: find value-bin containing rank KRANK + within-bin rank.  16 blocks x 256.
// ---------------------------------------------------------------------------
__global__ void select1() {
    int b = blockIdx.x;
    const uint4* h4 = (const uint4*)(g_hist + (size_t)b * NBINS);  // 4096 uint4
    __shared__ unsigned int partial[64];
    __shared__ unsigned int fine[256];
    __shared__ int s_chunk;
    __shared__ unsigned int s_rem;

    int warp = threadIdx.x >> 5;
    int lane = threadIdx.x & 31;

    #pragma unroll
    for (int it = 0; it < 8; it++) {
        int c = warp + 8 * it;
        uint4 v1 = h4[c * 64 + lane];
        uint4 v2 = h4[c * 64 + 32 + lane];
        unsigned int s = v1.x+v1.y+v1.z+v1.w + v2.x+v2.y+v2.z+v2.w;
        #pragma unroll
        for (int o = 16; o > 0; o >>= 1) s += __shfl_down_sync(0xFFFFFFFFu, s, o);
        if (lane == 0) partial[c] = s;
    }
    __syncthreads();

    if (threadIdx.x == 0) {
        unsigned int k = KRANK, cum = 0;
        int cb = 63;
        for (int j = 0; j < 64; j++) {
            if (k < cum + partial[j]) { cb = j; break; }
            cum += partial[j];
        }
        s_chunk = cb; s_rem = k - cum;
    }
    __syncthreads();

    int cb = s_chunk;
    fine[threadIdx.x] = g_hist[(size_t)b * NBINS + cb * 256 + threadIdx.x];
    __syncthreads();

    if (threadIdx.x == 0) {
        unsigned int k = s_rem, cum = 0;
        int fb = 255;
        for (int i = 0; i < 256; i++) {
            if (k < cum + fine[i]) { fb = i; break; }
            cum += fine[i];
        }
        g_bin[b]  = (unsigned int)(cb * 256 + fb);
        g_rank[b] = k - cum;        // within-bin rank (0-based)
    }
}

// ---------------------------------------------------------------------------
// K3: weighted L1 with bin-level mask; boundary-bin pixels get provisional
// 0.2 weight and are appended (gray, d) for exact correction in finalize.
// 1024 blocks (64/batch) x 256 thr; 16 px/thread.  y_true streamed (__ldcs)
// so L2-resident y_pred (from K1) survives.
// ---------------------------------------------------------------------------
__global__ void pass3_loss(const float* __restrict__ yt,
                           const float* __restrict__ yp) {
    int b = blockIdx.x >> 6;
    int r = blockIdx.x & 63;
    int t = threadIdx.x;
    unsigned int selbin = g_bin[b];

    size_t base4 = (size_t)b * 3 * (HW/4);
    const float4* p0 = (const float4*)yp + base4 + 0*(HW/4) + r*1024;
    const float4* p1 = (const float4*)yp + base4 + 1*(HW/4) + r*1024;
    const float4* p2 = (const float4*)yp + base4 + 2*(HW/4) + r*1024;
    const float4* q0 = (const float4*)yt + base4 + 0*(HW/4) + r*1024;
    const float4* q1 = (const float4*)yt + base4 + 1*(HW/4) + r*1024;
    const float4* q2 = (const float4*)yt + base4 + 2*(HW/4) + r*1024;

    float s = 0.0f;
    #pragma unroll
    for (int qq = 0; qq < 4; qq++) {
        int o = t + qq * 256;
        float4 a = p0[o], x = p1[o], y = p2[o];
        float4 u = __ldcs(&q0[o]);
        float4 v = __ldcs(&q1[o]);
        float4 w = __ldcs(&q2[o]);

        float gr[4], dd[4];
        gr[0] = (a.x + x.x + y.x) / 3.0f;
        gr[1] = (a.y + x.y + y.y) / 3.0f;
        gr[2] = (a.z + x.z + y.z) / 3.0f;
        gr[3] = (a.w + x.w + y.w) / 3.0f;
        dd[0] = fabsf(a.x-u.x) + fabsf(x.x-v.x) + fabsf(y.x-w.x);
        dd[1] = fabsf(a.y-u.y) + fabsf(x.y-v.y) + fabsf(y.y-w.y);
        dd[2] = fabsf(a.z-u.z) + fabsf(x.z-v.z) + fabsf(y.z-w.z);
        dd[3] = fabsf(a.w-u.w) + fabsf(x.w-v.w) + fabsf(y.w-w.w);

        #pragma unroll
        for (int i = 0; i < 4; i++) {
            unsigned int bn = gray_bin(gr[i]);
            float wt = (bn < selbin) ? 0.8f : 0.2f;
            if (bn == selbin) {
                unsigned int p = atomicAdd(&g_bnd_cnt[b], 1u);
                if (p < CAP) {
                    g_bnd_g[(size_t)b * CAP + p] = gr[i];
                    g_bnd_d[(size_t)b * CAP + p] = dd[i];
                }
            }
            s += wt * dd[i];
        }
    }

    #pragma unroll
    for (int o = 16; o > 0; o >>= 1)
        s += __shfl_down_sync(0xFFFFFFFFu, s, o);

    __shared__ float ws[8];
    int lane = t & 31;
    int warp = t >> 5;
    if (lane == 0) ws[warp] = s;
    __syncthreads();
    if (warp == 0) {
        float vv = (lane < 8) ? ws[lane] : 0.0f;
        #pragma unroll
        for (int o = 4; o > 0; o >>= 1)
            vv += __shfl_down_sync(0xFFFFFFFFu, vv, o);
        if (lane == 0) g_partial[blockIdx.x] = vv;
    }
}

// ---------------------------------------------------------------------------
// K4: all blocks zero hist; block 0: warp-per-batch exact boundary corrections
// (parallel, ~24 candidates each) + final double reduction.  256 blocks x 256.
// ---------------------------------------------------------------------------
__global__ void finalize(float* __restrict__ out) {
    int t = threadIdx.x;
    int zi = blockIdx.x * 256 + t;                 // 65536 uint4 = 1 MB hist
    ((uint4*)g_hist)[zi] = make_uint4(0u, 0u, 0u, 0u);

    if (blockIdx.x != 0) return;

    int lane = t & 31;
    int warp = t >> 5;

    // --- corrections: warp per batch (8 warps, 2 batches each) ---
    __shared__ float s_corr[NB];
    __shared__ float s_kth[NB];
    for (int bb = warp; bb < NB; bb += 8) {
        unsigned int n = g_bnd_cnt[bb];
        if (n > CAP) n = CAP;
        unsigned int k = g_rank[bb];
        const float* bg = g_bnd_g + (size_t)bb * CAP;
        const float* bd = g_bnd_d + (size_t)bb * CAP;

        for (unsigned int i = lane; i < n; i += 32) {
            float v = bg[i];
            unsigned int cl = 0, ce = 0;
            for (unsigned int j = 0; j < n; j++) {
                float w2 = bg[j];
                cl += (w2 < v);
                ce += (w2 == v);
            }
            if (cl <= k && k < cl + ce) s_kth[bb] = v;  // unique value
        }
        __syncwarp();
        float kth = s_kth[bb];
        float c = 0.0f;
        for (unsigned int i = lane; i < n; i += 32)
            if (bg[i] <= kth) c += bd[i];
        #pragma unroll
        for (int o = 16; o > 0; o >>= 1)
            c += __shfl_down_sync(0xFFFFFFFFu, c, o);
        if (lane == 0) s_corr[bb] = 0.6f * c;
    }
    __syncthreads();

    if (t < NB) g_bnd_cnt[t] = 0u;                 // reset for next replay

    // --- final reduction of 1024 partials + 16 corrections (double) ---
    double s = 0.0;
    #pragma unroll
    for (int i = 0; i < P3BLOCKS / 256; i++)
        s += (double)g_partial[t + i * 256];
    if (t < NB) s += (double)s_corr[t];

    #pragma unroll
    for (int o = 16; o > 0; o >>= 1)
        s += __shfl_down_sync(0xFFFFFFFFu, s, o);

    __shared__ double ds[8];
    if (lane == 0) ds[warp] = s;
    __syncthreads();
    if (warp == 0) {
        double v = (lane < 8) ? ds[lane] : 0.0;
        #pragma unroll
        for (int o = 4; o > 0; o >>= 1)
            v += __shfl_down_sync(0xFFFFFFFFu, v, o);
        if (lane == 0) out[0] = (float)(v / TOTAL_ELEMS);
    }
}

// ---------------------------------------------------------------------------
extern "C" void kernel_launch(void* const* d_in, const int* in_sizes, int n_in,
                              void* d_out, int out_size) {
    const float* y_true = (const float*)d_in[0];
    const float* y_pred = (const float*)d_in[1];
    float* out = (float*)d_out;

    pass1_hist<<<1024, 256>>>(y_pred);
    select1<<<NB, 256>>>();
    pass3_loss<<<P3BLOCKS, 256>>>(y_true, y_pred);
    finalize<<<256, 256>>>(out);
}

// round 10
// speedup vs baseline: 1.6981x; 1.4023x over previous
#include <cuda_runtime.h>
#include <math.h>

// Problem constants
#define NB      16
#define HW      262144           // 512*512
#define KRANK   104856u          // int(512*512*0.4 - 1)
#define NBINS   4096             // value-space bins: bin = min(4095, int(gray*4096))
#define CAP     2048             // per-batch boundary-pixel capacity (expected ~135)
#define SLAB    256              // smem staging capacity in finalize
#define P1BLOCKS 512             // 32 per batch
#define P3BLOCKS 1024            // 64 per batch
#define TOTAL_ELEMS (16.0*3.0*512.0*512.0)

// Device scratch (.bss zero-init; re-zeroed each replay by finalize)
__device__ unsigned int g_hist[NB * NBINS];       // 256 KB
__device__ unsigned int g_bin[NB];
__device__ unsigned int g_rank[NB];
__device__ unsigned int g_bnd_cnt[NB];
__device__ float        g_bnd_g[NB * CAP];
__device__ float        g_bnd_d[NB * CAP];
__device__ float        g_partial[P3BLOCKS];

__device__ __forceinline__ unsigned int gray_bin(float g) {
    int v = (int)(g * 4096.0f);
    if (v > NBINS - 1) v = NBINS - 1;
    if (v < 0) v = 0;
    return (unsigned int)v;
}

// ---------------------------------------------------------------------------
// K1: smem-privatized value-space histogram of gray = (c0+c1+c2)/3.
// 512 blocks (32/batch) x 256 thr; 32 px/thread; 16 KB smem hist per block.
// ---------------------------------------------------------------------------
__global__ void pass1_hist(const float* __restrict__ yp) {
    __shared__ unsigned int sh[NBINS];
    int b = blockIdx.x >> 5;          // 32 blocks per batch
    int r = blockIdx.x & 31;
    int t = threadIdx.x;

    #pragma unroll
    for (int i = t; i < NBINS; i += 256) sh[i] = 0u;
    __syncthreads();

    // each block: 2048 float4 per channel
    const float4* c0 = (const float4*)yp + (size_t)b * 3 * (HW/4) + 0 * (HW/4) + r * 2048;
    const float4* c1 = (const float4*)yp + (size_t)b * 3 * (HW/4) + 1 * (HW/4) + r * 2048;
    const float4* c2 = (const float4*)yp + (size_t)b * 3 * (HW/4) + 2 * (HW/4) + r * 2048;

    #pragma unroll
    for (int q = 0; q < 8; q++) {
        int o = t + q * 256;
        float4 a = c0[o], x = c1[o], y = c2[o];
        float g0 = (a.x + x.x + y.x) / 3.0f;
        float g1 = (a.y + x.y + y.y) / 3.0f;
        float g2 = (a.z + x.z + y.z) / 3.0f;
        float g3 = (a.w + x.w + y.w) / 3.0f;
        atomicAdd(&sh[gray_bin(g0)], 1u);
        atomicAdd(&sh[gray_bin(g1)], 1u);
        atomicAdd(&sh[gray_bin(g2)], 1u);
        atomicAdd(&sh[gray_bin(g3)], 1u);
    }
    __syncthreads();

    unsigned int* h = g_hist + (size_t)b * NBINS;
    #pragma unroll
    for (int i = t; i < NBINS; i += 256) {
        unsigned int c = sh[i];
        if (c) atomicAdd(&h[i], c);
    }
}

// ---------------------------------------------------------------------------
// K2: find value-bin containing rank KRANK + within-bin rank.  16 blocks x 256.
// Thread t sums bins [16t, 16t+16); fine scan smem-staged.
// ---------------------------------------------------------------------------
__global__ void select1() {
    int b = blockIdx.x;
    int t = threadIdx.x;
    const unsigned int* h = g_hist + (size_t)b * NBINS;
    const uint4* h4 = (const uint4*)h;            // 1024 uint4

    __shared__ unsigned int partial[256];
    __shared__ unsigned int fine[16];
    __shared__ int s_chunk;
    __shared__ unsigned int s_rem;

    unsigned int s = 0;
    #pragma unroll
    for (int j = 0; j < 4; j++) {
        uint4 v = h4[t * 4 + j];
        s += v.x + v.y + v.z + v.w;
    }
    partial[t] = s;
    __syncthreads();

    if (t == 0) {
        unsigned int k = KRANK, cum = 0;
        int cb = 255;
        for (int j = 0; j < 256; j++) {
            if (k < cum + partial[j]) { cb = j; break; }
            cum += partial[j];
        }
        s_chunk = cb; s_rem = k - cum;
    }
    __syncthreads();

    int cb = s_chunk;
    if (t < 16) fine[t] = h[cb * 16 + t];
    __syncthreads();

    if (t == 0) {
        unsigned int k = s_rem, cum = 0;
        int fb = 15;
        for (int i = 0; i < 16; i++) {
            if (k < cum + fine[i]) { fb = i; break; }
            cum += fine[i];
        }
        g_bin[b]  = (unsigned int)(cb * 16 + fb);
        g_rank[b] = k - cum;        // within-bin rank (0-based)
    }
}

// ---------------------------------------------------------------------------
// K3: weighted L1 with bin-level mask; boundary-bin pixels get provisional
// 0.2 weight and are appended (gray, d) for exact correction in finalize.
// 1024 blocks (64/batch) x 256 thr; 16 px/thread.  y_true streamed (__ldcs).
// ---------------------------------------------------------------------------
__global__ void pass3_loss(const float* __restrict__ yt,
                           const float* __restrict__ yp) {
    int b = blockIdx.x >> 6;
    int r = blockIdx.x & 63;
    int t = threadIdx.x;
    unsigned int selbin = g_bin[b];

    size_t base4 = (size_t)b * 3 * (HW/4);
    const float4* p0 = (const float4*)yp + base4 + 0*(HW/4) + r*1024;
    const float4* p1 = (const float4*)yp + base4 + 1*(HW/4) + r*1024;
    const float4* p2 = (const float4*)yp + base4 + 2*(HW/4) + r*1024;
    const float4* q0 = (const float4*)yt + base4 + 0*(HW/4) + r*1024;
    const float4* q1 = (const float4*)yt + base4 + 1*(HW/4) + r*1024;
    const float4* q2 = (const float4*)yt + base4 + 2*(HW/4) + r*1024;

    float s = 0.0f;
    #pragma unroll
    for (int qq = 0; qq < 4; qq++) {
        int o = t + qq * 256;
        float4 a = p0[o], x = p1[o], y = p2[o];
        float4 u = __ldcs(&q0[o]);
        float4 v = __ldcs(&q1[o]);
        float4 w = __ldcs(&q2[o]);

        float gr[4], dd[4];
        gr[0] = (a.x + x.x + y.x) / 3.0f;
        gr[1] = (a.y + x.y + y.y) / 3.0f;
        gr[2] = (a.z + x.z + y.z) / 3.0f;
        gr[3] = (a.w + x.w + y.w) / 3.0f;
        dd[0] = fabsf(a.x-u.x) + fabsf(x.x-v.x) + fabsf(y.x-w.x);
        dd[1] = fabsf(a.y-u.y) + fabsf(x.y-v.y) + fabsf(y.y-w.y);
        dd[2] = fabsf(a.z-u.z) + fabsf(x.z-v.z) + fabsf(y.z-w.z);
        dd[3] = fabsf(a.w-u.w) + fabsf(x.w-v.w) + fabsf(y.w-w.w);

        #pragma unroll
        for (int i = 0; i < 4; i++) {
            unsigned int bn = gray_bin(gr[i]);
            float wt = (bn < selbin) ? 0.8f : 0.2f;
            if (bn == selbin) {
                unsigned int p = atomicAdd(&g_bnd_cnt[b], 1u);
                if (p < CAP) {
                    g_bnd_g[(size_t)b * CAP + p] = gr[i];
                    g_bnd_d[(size_t)b * CAP + p] = dd[i];
                }
            }
            s += wt * dd[i];
        }
    }

    #pragma unroll
    for (int o = 16; o > 0; o >>= 1)
        s += __shfl_down_sync(0xFFFFFFFFu, s, o);

    __shared__ float ws[8];
    int lane = t & 31;
    int warp = t >> 5;
    if (lane == 0) ws[warp] = s;
    __syncthreads();
    if (warp == 0) {
        float vv = (lane < 8) ? ws[lane] : 0.0f;
        #pragma unroll
        for (int o = 4; o > 0; o >>= 1)
            vv += __shfl_down_sync(0xFFFFFFFFu, vv, o);
        if (lane == 0) g_partial[blockIdx.x] = vv;
    }
}

// ---------------------------------------------------------------------------
// K4: all blocks zero hist; block 0: warp-per-batch exact boundary corrections
// (smem-staged candidates) + final double reduction.  16 blocks x 512 thr.
// ---------------------------------------------------------------------------
__global__ void finalize(float* __restrict__ out) {
    int t = threadIdx.x;
    // zero hist: 16384 uint4 total, 2 per thread
    int zi = blockIdx.x * 512 + t;
    ((uint4*)g_hist)[zi] = make_uint4(0u, 0u, 0u, 0u);
    ((uint4*)g_hist)[zi + 8192] = make_uint4(0u, 0u, 0u, 0u);

    if (blockIdx.x != 0) return;

    int lane = t & 31;
    int warp = t >> 5;                 // 16 warps, one batch each

    __shared__ float s_corr[NB];
    __shared__ float s_kth[NB];
    __shared__ float sg[NB * SLAB];    // 16 KB
    __shared__ float sd[NB * SLAB];    // 16 KB

    {
        int bb = warp;
        unsigned int n = g_bnd_cnt[bb];
        if (n > CAP) n = CAP;
        unsigned int k = g_rank[bb];
        const float* bg = g_bnd_g + (size_t)bb * CAP;
        const float* bd = g_bnd_d + (size_t)bb * CAP;
        float c = 0.0f;

        if (n <= SLAB) {
            float* wg = sg + bb * SLAB;
            float* wd = sd + bb * SLAB;
            for (unsigned int i = lane; i < n; i += 32) {
                wg[i] = bg[i];
                wd[i] = bd[i];
            }
            __syncwarp();
            for (unsigned int i = lane; i < n; i += 32) {
                float v = wg[i];
                unsigned int cl = 0, ce = 0;
                for (unsigned int j = 0; j < n; j++) {
                    float w2 = wg[j];
                    cl += (w2 < v);
                    ce += (w2 == v);
                }
                if (cl <= k && k < cl + ce) s_kth[bb] = v;   // unique value
            }
            __syncwarp();
            float kth = s_kth[bb];
            for (unsigned int i = lane; i < n; i += 32)
                if (wg[i] <= kth) c += wd[i];
        } else {
            // fallback (practically unreachable): global-memory path
            for (unsigned int i = lane; i < n; i += 32) {
                float v = bg[i];
                unsigned int cl = 0, ce = 0;
                for (unsigned int j = 0; j < n; j++) {
                    float w2 = bg[j];
                    cl += (w2 < v);
                    ce += (w2 == v);
                }
                if (cl <= k && k < cl + ce) s_kth[bb] = v;
            }
            __syncwarp();
            float kth = s_kth[bb];
            for (unsigned int i = lane; i < n; i += 32)
                if (bg[i] <= kth) c += bd[i];
        }

        #pragma unroll
        for (int o = 16; o > 0; o >>= 1)
            c += __shfl_down_sync(0xFFFFFFFFu, c, o);
        if (lane == 0) {
            s_corr[bb] = 0.6f * c;
            g_bnd_cnt[bb] = 0u;            // reset for next replay
        }
    }
    __syncthreads();

    // --- final reduction of 1024 partials + 16 corrections (double) ---
    double s = (double)g_partial[t] + (double)g_partial[t + 512];
    if (t < NB) s += (double)s_corr[t];

    #pragma unroll
    for (int o = 16; o > 0; o >>= 1)
        s += __shfl_down_sync(0xFFFFFFFFu, s, o);

    __shared__ double ds[16];
    if (lane == 0) ds[warp] = s;
    __syncthreads();
    if (warp == 0) {
        double v = (lane < 16) ? ds[lane] : 0.0;
        #pragma unroll
        for (int o = 8; o > 0; o >>= 1)
            v += __shfl_down_sync(0xFFFFFFFFu, v, o);
        if (lane == 0) out[0] = (float)(v / TOTAL_ELEMS);
    }
}

// ---------------------------------------------------------------------------
extern "C" void kernel_launch(void* const* d_in, const int* in_sizes, int n_in,
                              void* d_out, int out_size) {
    const float* y_true = (const float*)d_in[0];
    const float* y_pred = (const float*)d_in[1];
    float* out = (float*)d_out;

    pass1_hist<<<P1BLOCKS, 256>>>(y_pred);
    select1<<<NB, 256>>>();
    pass3_loss<<<P3BLOCKS, 256>>>(y_true, y_pred);
    finalize<<<16, 512>>>(out);
}

// round 11
// speedup vs baseline: 2.0983x; 1.2357x over previous
#include <cuda_runtime.h>
#include <math.h>

// Problem constants
#define NB      16
#define HW      262144           // 512*512
#define KRANK   104856u          // int(512*512*0.4 - 1)
#define NBINS   4096             // value-space bins: bin = min(4095, int(gray*4096))
#define CAP     2048             // per-batch boundary-pixel capacity (expected ~140)
#define P1BLOCKS 512             // 32 per batch
#define P3BLOCKS 1024            // 64 per batch
#define TOTAL_ELEMS (16.0*3.0*512.0*512.0)

// Device scratch (.bss zero-init; re-zeroed each replay by correct())
__device__ unsigned int g_hist[NB * NBINS];       // 256 KB
__device__ unsigned int g_bin[NB];
__device__ unsigned int g_rank[NB];
__device__ unsigned int g_bnd_cnt[NB];
__device__ float        g_bnd_g[NB * CAP];
__device__ float        g_bnd_d[NB * CAP];
__device__ float        g_corr[NB];
__device__ float        g_partial[P3BLOCKS];

__device__ __forceinline__ unsigned int gray_bin(float g) {
    int v = (int)(g * 4096.0f);
    if (v > NBINS - 1) v = NBINS - 1;
    if (v < 0) v = 0;
    return (unsigned int)v;
}

// ---------------------------------------------------------------------------
// K1: smem-privatized value-space histogram of gray = (c0+c1+c2)/3.
// 512 blocks (32/batch) x 256 thr; 32 px/thread; 16 KB smem hist per block.
// ---------------------------------------------------------------------------
__global__ void pass1_hist(const float* __restrict__ yp) {
    __shared__ unsigned int sh[NBINS];
    int b = blockIdx.x >> 5;          // 32 blocks per batch
    int r = blockIdx.x & 31;
    int t = threadIdx.x;

    #pragma unroll
    for (int i = t; i < NBINS; i += 256) sh[i] = 0u;
    __syncthreads();

    const float4* c0 = (const float4*)yp + (size_t)b * 3 * (HW/4) + 0 * (HW/4) + r * 2048;
    const float4* c1 = (const float4*)yp + (size_t)b * 3 * (HW/4) + 1 * (HW/4) + r * 2048;
    const float4* c2 = (const float4*)yp + (size_t)b * 3 * (HW/4) + 2 * (HW/4) + r * 2048;

    #pragma unroll
    for (int q = 0; q < 8; q++) {
        int o = t + q * 256;
        float4 a = c0[o], x = c1[o], y = c2[o];
        float g0 = (a.x + x.x + y.x) / 3.0f;
        float g1 = (a.y + x.y + y.y) / 3.0f;
        float g2 = (a.z + x.z + y.z) / 3.0f;
        float g3 = (a.w + x.w + y.w) / 3.0f;
        atomicAdd(&sh[gray_bin(g0)], 1u);
        atomicAdd(&sh[gray_bin(g1)], 1u);
        atomicAdd(&sh[gray_bin(g2)], 1u);
        atomicAdd(&sh[gray_bin(g3)], 1u);
    }
    __syncthreads();

    unsigned int* h = g_hist + (size_t)b * NBINS;
    #pragma unroll
    for (int i = t; i < NBINS; i += 256) {
        unsigned int c = sh[i];
        if (c) atomicAdd(&h[i], c);
    }
}

// ---------------------------------------------------------------------------
// K2: find value-bin containing rank KRANK + within-bin rank.  16 blocks x 256.
// ---------------------------------------------------------------------------
__global__ void select1() {
    int b = blockIdx.x;
    int t = threadIdx.x;
    const unsigned int* h = g_hist + (size_t)b * NBINS;
    const uint4* h4 = (const uint4*)h;            // 1024 uint4

    __shared__ unsigned int partial[256];
    __shared__ unsigned int fine[16];
    __shared__ int s_chunk;
    __shared__ unsigned int s_rem;

    unsigned int s = 0;
    #pragma unroll
    for (int j = 0; j < 4; j++) {
        uint4 v = h4[t * 4 + j];
        s += v.x + v.y + v.z + v.w;
    }
    partial[t] = s;
    __syncthreads();

    if (t == 0) {
        unsigned int k = KRANK, cum = 0;
        int cb = 255;
        for (int j = 0; j < 256; j++) {
            if (k < cum + partial[j]) { cb = j; break; }
            cum += partial[j];
        }
        s_chunk = cb; s_rem = k - cum;
    }
    __syncthreads();

    int cb = s_chunk;
    if (t < 16) fine[t] = h[cb * 16 + t];
    __syncthreads();

    if (t == 0) {
        unsigned int k = s_rem, cum = 0;
        int fb = 15;
        for (int i = 0; i < 16; i++) {
            if (k < cum + fine[i]) { fb = i; break; }
            cum += fine[i];
        }
        g_bin[b]  = (unsigned int)(cb * 16 + fb);
        g_rank[b] = k - cum;        // within-bin rank (0-based)
    }
}

// ---------------------------------------------------------------------------
// K3: weighted L1 with bin-level mask; boundary-bin pixels get provisional
// 0.2 weight and are appended (gray, d) for exact correction later.
// 1024 blocks (64/batch) x 256 thr; 16 px/thread.  y_true streamed (__ldcs).
// ---------------------------------------------------------------------------
__global__ void pass3_loss(const float* __restrict__ yt,
                           const float* __restrict__ yp) {
    int b = blockIdx.x >> 6;
    int r = blockIdx.x & 63;
    int t = threadIdx.x;
    unsigned int selbin = g_bin[b];

    size_t base4 = (size_t)b * 3 * (HW/4);
    const float4* p0 = (const float4*)yp + base4 + 0*(HW/4) + r*1024;
    const float4* p1 = (const float4*)yp + base4 + 1*(HW/4) + r*1024;
    const float4* p2 = (const float4*)yp + base4 + 2*(HW/4) + r*1024;
    const float4* q0 = (const float4*)yt + base4 + 0*(HW/4) + r*1024;
    const float4* q1 = (const float4*)yt + base4 + 1*(HW/4) + r*1024;
    const float4* q2 = (const float4*)yt + base4 + 2*(HW/4) + r*1024;

    float s = 0.0f;
    #pragma unroll
    for (int qq = 0; qq < 4; qq++) {
        int o = t + qq * 256;
        float4 a = p0[o], x = p1[o], y = p2[o];
        float4 u = __ldcs(&q0[o]);
        float4 v = __ldcs(&q1[o]);
        float4 w = __ldcs(&q2[o]);

        float gr[4], dd[4];
        gr[0] = (a.x + x.x + y.x) / 3.0f;
        gr[1] = (a.y + x.y + y.y) / 3.0f;
        gr[2] = (a.z + x.z + y.z) / 3.0f;
        gr[3] = (a.w + x.w + y.w) / 3.0f;
        dd[0] = fabsf(a.x-u.x) + fabsf(x.x-v.x) + fabsf(y.x-w.x);
        dd[1] = fabsf(a.y-u.y) + fabsf(x.y-v.y) + fabsf(y.y-w.y);
        dd[2] = fabsf(a.z-u.z) + fabsf(x.z-v.z) + fabsf(y.z-w.z);
        dd[3] = fabsf(a.w-u.w) + fabsf(x.w-v.w) + fabsf(y.w-w.w);

        #pragma unroll
        for (int i = 0; i < 4; i++) {
            unsigned int bn = gray_bin(gr[i]);
            float wt = (bn < selbin) ? 0.8f : 0.2f;
            if (bn == selbin) {
                unsigned int p = atomicAdd(&g_bnd_cnt[b], 1u);
                if (p < CAP) {
                    g_bnd_g[(size_t)b * CAP + p] = gr[i];
                    g_bnd_d[(size_t)b * CAP + p] = dd[i];
                }
            }
            s += wt * dd[i];
        }
    }

    #pragma unroll
    for (int o = 16; o > 0; o >>= 1)
        s += __shfl_down_sync(0xFFFFFFFFu, s, o);

    __shared__ float ws[8];
    int lane = t & 31;
    int warp = t >> 5;
    if (lane == 0) ws[warp] = s;
    __syncthreads();
    if (warp == 0) {
        float vv = (lane < 8) ? ws[lane] : 0.0f;
        #pragma unroll
        for (int o = 4; o > 0; o >>= 1)
            vv += __shfl_down_sync(0xFFFFFFFFu, vv, o);
        if (lane == 0) g_partial[blockIdx.x] = vv;
    }
}

// ---------------------------------------------------------------------------
// K4: block-per-batch exact boundary correction (thread-per-candidate) +
// zero this batch's hist slice + reset counters.  16 blocks x 256 thr.
// ---------------------------------------------------------------------------
__global__ void correct() {
    int b = blockIdx.x;
    int t = threadIdx.x;

    // zero hist slice for next replay: 4096 uints = 1024 uint4
    {
        uint4* hz = (uint4*)(g_hist + (size_t)b * NBINS);
        #pragma unroll
        for (int j = 0; j < 4; j++)
            hz[t + j * 256] = make_uint4(0u, 0u, 0u, 0u);
    }

    __shared__ float sg[CAP];          // 8 KB
    __shared__ float sd[CAP];          // 8 KB
    __shared__ float s_kth;
    __shared__ unsigned int s_n;

    if (t == 0) {
        unsigned int n = g_bnd_cnt[b];
        s_n = (n > CAP) ? CAP : n;
        g_bnd_cnt[b] = 0u;             // reset for next replay
    }
    __syncthreads();
    unsigned int n = s_n;

    for (unsigned int i = t; i < n; i += 256) {
        sg[i] = g_bnd_g[(size_t)b * CAP + i];
        sd[i] = g_bnd_d[(size_t)b * CAP + i];
    }
    __syncthreads();

    unsigned int k = g_rank[b];
    for (unsigned int i = t; i < n; i += 256) {
        float v = sg[i];
        unsigned int cl = 0, ce = 0;
        for (unsigned int j = 0; j < n; j++) {   // smem broadcast reads
            float w2 = sg[j];
            cl += (w2 < v);
            ce += (w2 == v);
        }
        if (cl <= k && k < cl + ce) s_kth = v;   // unique value
    }
    __syncthreads();

    float kth = s_kth;
    float c = 0.0f;
    for (unsigned int i = t; i < n; i += 256)
        if (sg[i] <= kth) c += sd[i];

    #pragma unroll
    for (int o = 16; o > 0; o >>= 1)
        c += __shfl_down_sync(0xFFFFFFFFu, c, o);

    __shared__ float ws[8];
    int lane = t & 31;
    int warp = t >> 5;
    if (lane == 0) ws[warp] = c;
    __syncthreads();
    if (warp == 0) {
        float vv = (lane < 8) ? ws[lane] : 0.0f;
        #pragma unroll
        for (int o = 4; o > 0; o >>= 1)
            vv += __shfl_down_sync(0xFFFFFFFFu, vv, o);
        if (lane == 0) g_corr[b] = 0.6f * vv;
    }
}

// ---------------------------------------------------------------------------
// K5: final reduction of 1024 partials + 16 corrections (double).  1 x 512.
// ---------------------------------------------------------------------------
__global__ void finalize(float* __restrict__ out) {
    int t = threadIdx.x;
    double s = (double)g_partial[t] + (double)g_partial[t + 512];
    if (t < NB) s += (double)g_corr[t];

    #pragma unroll
    for (int o = 16; o > 0; o >>= 1)
        s += __shfl_down_sync(0xFFFFFFFFu, s, o);

    __shared__ double ds[16];
    int lane = t & 31;
    int warp = t >> 5;
    if (lane == 0) ds[warp] = s;
    __syncthreads();
    if (warp == 0) {
        double v = (lane < 16) ? ds[lane] : 0.0;
        #pragma unroll
        for (int o = 8; o > 0; o >>= 1)
            v += __shfl_down_sync(0xFFFFFFFFu, v, o);
        if (lane == 0) out[0] = (float)(v / TOTAL_ELEMS);
    }
}

// ---------------------------------------------------------------------------
extern "C" void kernel_launch(void* const* d_in, const int* in_sizes, int n_in,
                              void* d_out, int out_size) {
    const float* y_true = (const float*)d_in[0];
    const float* y_pred = (const float*)d_in[1];
    float* out = (float*)d_out;

    pass1_hist<<<P1BLOCKS, 256>>>(y_pred);
    select1<<<NB, 256>>>();
    pass3_loss<<<P3BLOCKS, 256>>>(y_true, y_pred);
    correct<<<NB, 256>>>();
    finalize<<<1, 512>>>(out);
}